// round 9
// baseline (speedup 1.0000x reference)
#include <cuda_runtime.h>
#include <cstddef>
#include <cstdint>

// Problem dims
#define TT 512
#define BB 512
#define FF 128
#define HH 256
#define OO 128

// Scan config: 128 CTAs x 4 batch rows
#define MR 4
#define NCTA (BB / MR)
// k-rows of each weight matrix cached in SMEM (smem = 3*KC*HH*4 + 20KB <= 232448)
#define KC 68

// -------- device scratch (allocation-free: __device__ globals) --------
__device__ float g_wx[(size_t)TT * BB * HH];   // [t][b][h] input projection incl. b_in
__device__ float g_whid_t[HH * HH];            // (2*W_hid)^T as [k][n]
__device__ float g_w2_t[HH * HH];              // W2^T as [k][n]
__device__ float g_w3_t[HH * HH];              // W3^T as [k][n]
__device__ float g_wot[HH * OO];               // W_out^T as [k][o]

// ---------- f32x2 helpers ----------
__device__ __forceinline__ void fma2(unsigned long long& acc,
                                     unsigned long long a,
                                     unsigned long long b) {
    asm("fma.rn.f32x2 %0, %1, %2, %0;" : "+l"(acc) : "l"(a), "l"(b));
}
__device__ __forceinline__ unsigned long long bcast2(float w) {
    unsigned long long r;
    asm("mov.b64 %0, {%1, %1};" : "=l"(r) : "f"(w));
    return r;
}
__device__ __forceinline__ void unpack2(unsigned long long v, float& lo, float& hi) {
    asm("mov.b64 {%0, %1}, %2;" : "=f"(lo), "=f"(hi) : "l"(v));
}
__device__ __forceinline__ void lds_v2u64(uint32_t saddr,
                                          unsigned long long& a,
                                          unsigned long long& b) {
    asm("ld.shared.v2.u64 {%0, %1}, [%2];" : "=l"(a), "=l"(b) : "r"(saddr));
}

// ---------------------------------------------------------------------
// Kernel 0: transpose weights into [k][n] layout (coalesced writes).
// Folds the (h + h) into W_hid by pre-scaling x2.
// ---------------------------------------------------------------------
__global__ void k_transpose(const float* __restrict__ Whid,
                            const float* __restrict__ W2,
                            const float* __restrict__ W3,
                            const float* __restrict__ Wout) {
    int idx = blockIdx.x * 256 + threadIdx.x;   // 256x256 = 65536 = HH*HH
    if (idx < HH * HH) {
        int k = idx >> 8;
        int n = idx & 255;
        g_whid_t[idx] = 2.0f * Whid[n * HH + k];
        g_w2_t[idx]   = W2[n * HH + k];
        g_w3_t[idx]   = W3[n * HH + k];
    }
    if (idx < HH * OO) {
        int k = idx >> 7;
        int o = idx & 127;
        g_wot[idx] = Wout[o * HH + k];
    }
}

// ---------------------------------------------------------------------
// Kernel 1: WX[t][b][:] = x0[b,:,t] @ W_in.T + b_in   for all t, b.
// Grid (T/64, B). CTA: 64 t x 256 h for one b. f32x2 over t-pairs.
// ---------------------------------------------------------------------
#define WINT_STRIDE 260   // padded W_in^T rows in SMEM
#define WX_SMEM ((FF * WINT_STRIDE + FF * 64) * 4)

__global__ void __launch_bounds__(256) k_wx(const float* __restrict__ x0,
                                            const float* __restrict__ Win,
                                            const float* __restrict__ bin) {
    extern __shared__ float sm[];
    float* wint = sm;                       // [k=128][h=256] stride 260
    float* xs   = sm + FF * WINT_STRIDE;    // [f=128][tt=64]

    int tb = blockIdx.x;     // t-block (0..7)
    int b  = blockIdx.y;     // batch row
    int tid = threadIdx.x;

    // W_in transposed: Win[h][k] -> wint[k][h]
    for (int e = tid; e < HH * FF; e += 256) {
        int h = e >> 7, k = e & 127;
        wint[k * WINT_STRIDE + h] = Win[e];
    }
    // x tile: x0[b][f][tb*64 + t] (t contiguous -> coalesced)
    const float* xb = x0 + (size_t)b * FF * TT + (size_t)tb * 64;
    for (int e = tid; e < FF * 64; e += 256) {
        int f = e >> 6, t = e & 63;
        xs[f * 64 + t] = xb[(size_t)f * TT + t];
    }
    __syncthreads();

    int ttg = tid & 3;         // 4 t-groups of 16
    int htg = tid >> 2;        // 64 h-groups of 4
    int h0 = htg * 4;
    int t0 = ttg * 16;

    uint32_t xs_base = (uint32_t)__cvta_generic_to_shared(xs) + (uint32_t)(t0 * 4);

    // acc2[j][i2]: h = h0+j, t-pair (t0+2*i2, t0+2*i2+1)
    unsigned long long acc2[4][8];
    #pragma unroll
    for (int j = 0; j < 4; ++j)
        #pragma unroll
        for (int i = 0; i < 8; ++i) acc2[j][i] = 0ull;

    #pragma unroll 2
    for (int k = 0; k < FF; ++k) {
        float4 w4 = *(const float4*)&wint[k * WINT_STRIDE + h0];
        unsigned long long ww[4] = {bcast2(w4.x), bcast2(w4.y), bcast2(w4.z), bcast2(w4.w)};
        unsigned long long xp[8];
        uint32_t row = xs_base + (uint32_t)(k * 64 * 4);
        lds_v2u64(row,      xp[0], xp[1]);
        lds_v2u64(row + 16, xp[2], xp[3]);
        lds_v2u64(row + 32, xp[4], xp[5]);
        lds_v2u64(row + 48, xp[6], xp[7]);
        #pragma unroll
        for (int j = 0; j < 4; ++j)
            #pragma unroll
            for (int i = 0; i < 8; ++i)
                fma2(acc2[j][i], xp[i], ww[j]);
    }

    float bias[4];
    #pragma unroll
    for (int j = 0; j < 4; ++j) bias[j] = bin[h0 + j];

    // Store wx[t][b][h0..h0+3] (float4 over h)
    #pragma unroll
    for (int i = 0; i < 8; ++i) {
        float lo[4], hi[4];
        #pragma unroll
        for (int j = 0; j < 4; ++j) unpack2(acc2[j][i], lo[j], hi[j]);
        int tg0 = tb * 64 + t0 + 2 * i;
        float4 v0 = make_float4(lo[0] + bias[0], lo[1] + bias[1], lo[2] + bias[2], lo[3] + bias[3]);
        float4 v1 = make_float4(hi[0] + bias[0], hi[1] + bias[1], hi[2] + bias[2], hi[3] + bias[3]);
        *(float4*)&g_wx[((size_t)tg0 * BB + b) * HH + h0]       = v0;
        *(float4*)&g_wx[((size_t)(tg0 + 1) * BB + b) * HH + h0] = v1;
    }
}

// ---------------------------------------------------------------------
// Kernel 2: persistent scan. 128 CTAs x 256 threads; CTA c owns batch
// rows c*4..c*4+3 for all 512 steps. Thread n owns output column n.
// Activations in SMEM as [k][4] (float4 rows) -> broadcast ld.v2.u64
// pairs feed fma.rn.f32x2. First KC k-rows of each weight cached in
// SMEM, rest streamed from L2 (unroll 16 -> MLP for BW saturation).
// wx staged with a 2-deep double buffer prefetched a step ahead.
// ---------------------------------------------------------------------
#define SCAN_SMEM ((3 * KC * HH + 3 * HH * 4 + 2 * 4 * HH) * 4)   // 229376 B <= 232448

__device__ __forceinline__ void gemm4x2(const float* __restrict__ ws,   // SMEM [KC][HH]
                                        const float* __restrict__ wg,   // gmem [HH][HH]
                                        const float* __restrict__ act,  // SMEM [k][4]
                                        int n, float* accf) {
    unsigned long long acc01 = 0ull, acc23 = 0ull;
    uint32_t abase = (uint32_t)__cvta_generic_to_shared(act);
    #pragma unroll 4
    for (int k = 0; k < KC; ++k) {
        unsigned long long a01, a23;
        lds_v2u64(abase + (uint32_t)(k * 16), a01, a23);
        unsigned long long ww = bcast2(ws[k * HH + n]);
        fma2(acc01, a01, ww);
        fma2(acc23, a23, ww);
    }
    #pragma unroll 16
    for (int k = KC; k < HH; ++k) {
        unsigned long long a01, a23;
        lds_v2u64(abase + (uint32_t)(k * 16), a01, a23);
        unsigned long long ww = bcast2(__ldg(wg + k * HH + n));
        fma2(acc01, a01, ww);
        fma2(acc23, a23, ww);
    }
    unpack2(acc01, accf[0], accf[1]);
    unpack2(acc23, accf[2], accf[3]);
}

__global__ void __launch_bounds__(256) k_scan(const float* __restrict__ h0,
                                              const float* __restrict__ bhid,
                                              const float* __restrict__ b2v,
                                              const float* __restrict__ b3v,
                                              const float* __restrict__ bout,
                                              float* __restrict__ out) {
    extern __shared__ float sm[];
    float* cwh  = sm;                    // [KC][HH] cached 2*W_hid^T
    float* cw2  = sm + KC * HH;          // [KC][HH] cached W2^T
    float* cw3  = sm + 2 * KC * HH;      // [KC][HH] cached W3^T
    float* hs   = sm + 3 * KC * HH;      // [HH][4]  h
    float* actA = hs + HH * 4;           // [HH][4]
    float* actB = actA + HH * 4;         // [HH][4]
    float* wxs  = actB + HH * 4;         // [2][4*HH] double buffer

    int n = threadIdx.x;                 // output column
    int c = blockIdx.x;                  // row block

    // Fill weight cache
    for (int e = n; e < KC * HH; e += 256) {
        cwh[e] = g_whid_t[e];
        cw2[e] = g_w2_t[e];
        cw3[e] = g_w3_t[e];
    }
    // Stage wx for t=0 into buffer 0
    {
        const float* wxg0 = g_wx + (size_t)c * 4 * HH;
        #pragma unroll
        for (int i = 0; i < 4; ++i) wxs[n + i * 256] = wxg0[n + i * 256];
    }

    float h[4];
    #pragma unroll
    for (int r = 0; r < 4; ++r) h[r] = h0[(size_t)(c * 4 + r) * HH + n];
    *(float4*)&hs[n * 4] = make_float4(h[0], h[1], h[2], h[3]);

    float bh = bhid[n], bv2 = b2v[n], bv3 = b3v[n];
    __syncthreads();

    for (int t = 0; t < TT; ++t) {
        float* cur = wxs + (t & 1) * (4 * HH);
        // Prefetch next step's wx into registers (whole step of latency slack)
        float pre[4];
        bool hasnext = (t + 1) < TT;
        if (hasnext) {
            const float* g = g_wx + ((size_t)(t + 1) * BB + (size_t)c * 4) * HH;
            #pragma unroll
            for (int i = 0; i < 4; ++i) pre[i] = __ldg(g + n + i * 256);
        }

        float acc[4];
        // G1: f1 = relu(2h @ W_hid^T + b_hid + wx)   (x2 folded into weights)
        gemm4x2(cwh, g_whid_t, hs, n, acc);
        {
            float f0 = fmaxf(acc[0] + bh + cur[n], 0.0f);
            float f1 = fmaxf(acc[1] + bh + cur[HH + n], 0.0f);
            float f2 = fmaxf(acc[2] + bh + cur[2 * HH + n], 0.0f);
            float f3 = fmaxf(acc[3] + bh + cur[3 * HH + n], 0.0f);
            *(float4*)&actA[n * 4] = make_float4(f0, f1, f2, f3);
        }
        __syncthreads();

        // G2: g = relu(f1 @ W2^T + b2)
        gemm4x2(cw2, g_w2_t, actA, n, acc);
        *(float4*)&actB[n * 4] = make_float4(fmaxf(acc[0] + bv2, 0.0f),
                                             fmaxf(acc[1] + bv2, 0.0f),
                                             fmaxf(acc[2] + bv2, 0.0f),
                                             fmaxf(acc[3] + bv2, 0.0f));
        __syncthreads();

        // G3: fn = relu(g @ W3^T + b3);  h <- 0.98 h + 0.01 fn
        gemm4x2(cw3, g_w3_t, actB, n, acc);
        #pragma unroll
        for (int r = 0; r < 4; ++r) {
            float fn = fmaxf(acc[r] + bv3, 0.0f);
            h[r] = 0.98f * h[r] + 0.01f * fn;
        }
        // hs last read in G1 (guarded by sync after G1) -> safe to overwrite
        *(float4*)&hs[n * 4] = make_float4(h[0], h[1], h[2], h[3]);
        // Commit prefetched wx into the alternate buffer (last read: step t-1 G1)
        if (hasnext) {
            float* nb = wxs + ((t + 1) & 1) * (4 * HH);
            #pragma unroll
            for (int i = 0; i < 4; ++i) nb[n + i * 256] = pre[i];
        }
        __syncthreads();
    }

    // h1 -> out[OO*BB + b*HH + n]
    #pragma unroll
    for (int r = 0; r < 4; ++r)
        out[(size_t)OO * BB + (size_t)(c * 4 + r) * HH + n] = h[r];

    // y1 = h1 @ W_out^T + b_out -> out[b*OO + o]
    if (n < OO) {
        float bo = bout[n];
        float acc[4] = {bo, bo, bo, bo};
        #pragma unroll 8
        for (int k = 0; k < HH; ++k) {
            float4 a = *(const float4*)&hs[k * 4];
            float w = __ldg(g_wot + k * OO + n);
            acc[0] += a.x * w; acc[1] += a.y * w; acc[2] += a.z * w; acc[3] += a.w * w;
        }
        #pragma unroll
        for (int r = 0; r < 4; ++r)
            out[(size_t)(c * 4 + r) * OO + n] = acc[r];
    }
}

// ---------------------------------------------------------------------
// Launch: 3 kernels, default stream (graph-capturable, alloc-free).
// Inputs: x0,h0,W_in,b_in,W_hid,b_hid,W2,b2,W3,b3,W_out,b_out
// Output: y1 [512,128] then h1 [512,256] (196608 floats).
// ---------------------------------------------------------------------
extern "C" void kernel_launch(void* const* d_in, const int* in_sizes, int n_in,
                              void* d_out, int out_size) {
    const float* x0   = (const float*)d_in[0];
    const float* h0   = (const float*)d_in[1];
    const float* Win  = (const float*)d_in[2];
    const float* bin  = (const float*)d_in[3];
    const float* Whid = (const float*)d_in[4];
    const float* bhid = (const float*)d_in[5];
    const float* W2   = (const float*)d_in[6];
    const float* b2   = (const float*)d_in[7];
    const float* W3   = (const float*)d_in[8];
    const float* b3   = (const float*)d_in[9];
    const float* Wout = (const float*)d_in[10];
    const float* bout = (const float*)d_in[11];
    float* out = (float*)d_out;

    cudaFuncSetAttribute(k_wx,   cudaFuncAttributeMaxDynamicSharedMemorySize, WX_SMEM);
    cudaFuncSetAttribute(k_scan, cudaFuncAttributeMaxDynamicSharedMemorySize, SCAN_SMEM);

    k_transpose<<<256, 256>>>(Whid, W2, W3, Wout);
    k_wx<<<dim3(TT / 64, BB), 256, WX_SMEM>>>(x0, Win, bin);
    k_scan<<<NCTA, 256, SCAN_SMEM>>>(h0, bhid, b2, b3, bout, out);

    (void)in_sizes; (void)n_in; (void)out_size;
}

// round 10
// speedup vs baseline: 1.1254x; 1.1254x over previous
#include <cuda_runtime.h>
#include <cstddef>
#include <cstdint>

// Problem dims
#define TT 512
#define BB 512
#define FF 128
#define HH 256
#define OO 128

// Scan config: 128 CTAs x 4 batch rows, 512 threads (k-split in 2 halves)
#define MR 4
#define NCTA (BB / MR)
#define STH 512
// cached k-rows per half per matrix (total cached rows per matrix = 2*KC2)
#define KC2 32
// scan time segments (more k_scan launches -> ncu -s 5 lands on scan)
#define NSEG 4
#define SEGT (TT / NSEG)

// -------- device scratch (allocation-free: __device__ globals) --------
__device__ float g_wx[(size_t)TT * BB * HH];   // [t][b][h] input projection incl. b_in
__device__ float g_whid_t[HH * HH];            // (2*W_hid)^T as [k][n]
__device__ float g_w2_t[HH * HH];              // W2^T as [k][n]
__device__ float g_w3_t[HH * HH];              // W3^T as [k][n]
__device__ float g_wot[HH * OO];               // W_out^T as [k][o]
__device__ float g_h[BB * HH];                 // h state between scan segments

// ---------- f32x2 helpers ----------
__device__ __forceinline__ void fma2(unsigned long long& acc,
                                     unsigned long long a,
                                     unsigned long long b) {
    asm("fma.rn.f32x2 %0, %1, %2, %0;" : "+l"(acc) : "l"(a), "l"(b));
}
__device__ __forceinline__ unsigned long long bcast2(float w) {
    unsigned long long r;
    asm("mov.b64 %0, {%1, %1};" : "=l"(r) : "f"(w));
    return r;
}
__device__ __forceinline__ void unpack2(unsigned long long v, float& lo, float& hi) {
    asm("mov.b64 {%0, %1}, %2;" : "=f"(lo), "=f"(hi) : "l"(v));
}
__device__ __forceinline__ void lds_v2u64(uint32_t saddr,
                                          unsigned long long& a,
                                          unsigned long long& b) {
    asm("ld.shared.v2.u64 {%0, %1}, [%2];" : "=l"(a), "=l"(b) : "r"(saddr));
}

// ---------------------------------------------------------------------
// Kernel 0: transpose weights into [k][n] layout; fold (h+h) as x2.
// ---------------------------------------------------------------------
__global__ void k_transpose(const float* __restrict__ Whid,
                            const float* __restrict__ W2,
                            const float* __restrict__ W3,
                            const float* __restrict__ Wout) {
    int idx = blockIdx.x * 256 + threadIdx.x;
    if (idx < HH * HH) {
        int k = idx >> 8;
        int n = idx & 255;
        g_whid_t[idx] = 2.0f * Whid[n * HH + k];
        g_w2_t[idx]   = W2[n * HH + k];
        g_w3_t[idx]   = W3[n * HH + k];
    }
    if (idx < HH * OO) {
        int k = idx >> 7;
        int o = idx & 127;
        g_wot[idx] = Wout[o * HH + k];
    }
}

// ---------------------------------------------------------------------
// Kernel 1: WX[t][b][:] = x0[b,:,t] @ W_in.T + b_in  (unchanged; ~0.3ms)
// ---------------------------------------------------------------------
#define WINT_STRIDE 260
#define WX_SMEM ((FF * WINT_STRIDE + FF * 64) * 4)

__global__ void __launch_bounds__(256) k_wx(const float* __restrict__ x0,
                                            const float* __restrict__ Win,
                                            const float* __restrict__ bin) {
    extern __shared__ float sm[];
    float* wint = sm;
    float* xs   = sm + FF * WINT_STRIDE;

    int tb = blockIdx.x;
    int b  = blockIdx.y;
    int tid = threadIdx.x;

    for (int e = tid; e < HH * FF; e += 256) {
        int h = e >> 7, k = e & 127;
        wint[k * WINT_STRIDE + h] = Win[e];
    }
    const float* xb = x0 + (size_t)b * FF * TT + (size_t)tb * 64;
    for (int e = tid; e < FF * 64; e += 256) {
        int f = e >> 6, t = e & 63;
        xs[f * 64 + t] = xb[(size_t)f * TT + t];
    }
    __syncthreads();

    int ttg = tid & 3;
    int htg = tid >> 2;
    int h0 = htg * 4;
    int t0 = ttg * 16;

    uint32_t xs_base = (uint32_t)__cvta_generic_to_shared(xs) + (uint32_t)(t0 * 4);

    unsigned long long acc2[4][8];
    #pragma unroll
    for (int j = 0; j < 4; ++j)
        #pragma unroll
        for (int i = 0; i < 8; ++i) acc2[j][i] = 0ull;

    #pragma unroll 2
    for (int k = 0; k < FF; ++k) {
        float4 w4 = *(const float4*)&wint[k * WINT_STRIDE + h0];
        unsigned long long ww[4] = {bcast2(w4.x), bcast2(w4.y), bcast2(w4.z), bcast2(w4.w)};
        unsigned long long xp[8];
        uint32_t row = xs_base + (uint32_t)(k * 64 * 4);
        lds_v2u64(row,      xp[0], xp[1]);
        lds_v2u64(row + 16, xp[2], xp[3]);
        lds_v2u64(row + 32, xp[4], xp[5]);
        lds_v2u64(row + 48, xp[6], xp[7]);
        #pragma unroll
        for (int j = 0; j < 4; ++j)
            #pragma unroll
            for (int i = 0; i < 8; ++i)
                fma2(acc2[j][i], xp[i], ww[j]);
    }

    float bias[4];
    #pragma unroll
    for (int j = 0; j < 4; ++j) bias[j] = bin[h0 + j];

    #pragma unroll
    for (int i = 0; i < 8; ++i) {
        float lo[4], hi[4];
        #pragma unroll
        for (int j = 0; j < 4; ++j) unpack2(acc2[j][i], lo[j], hi[j]);
        int tg0 = tb * 64 + t0 + 2 * i;
        float4 v0 = make_float4(lo[0] + bias[0], lo[1] + bias[1], lo[2] + bias[2], lo[3] + bias[3]);
        float4 v1 = make_float4(hi[0] + bias[0], hi[1] + bias[1], hi[2] + bias[2], hi[3] + bias[3]);
        *(float4*)&g_wx[((size_t)tg0 * BB + b) * HH + h0]       = v0;
        *(float4*)&g_wx[((size_t)(tg0 + 1) * BB + b) * HH + h0] = v1;
    }
}

// ---------------------------------------------------------------------
// Kernel 2: persistent scan SEGMENT over t in [t0,t1). 128 CTAs x 512
// threads. Thread (g = tid>>8, n = tid&255): partial dot over k-half
// g for output column n; halves combined via a SMEM partial buffer.
// 16 warps/SM -> hide streamed-LDG latency. Weight cache: 2*KC2 rows
// per matrix in SMEM; rest streamed from L2. h handed between segments
// through g_h. Output written by the last segment.
// SMEM: 3*64*256 + 3*256*4 + 2*1024 + 256*4 floats = 221184 B
// ---------------------------------------------------------------------
#define SCAN_SMEM ((3 * 2 * KC2 * HH + 3 * HH * 4 + 2 * 4 * HH + HH * 4) * 4)

__device__ __forceinline__ void gemm_half(const float* __restrict__ cw,   // SMEM [2*KC2][HH]
                                          const float* __restrict__ wg,   // gmem [HH][HH]
                                          const float* __restrict__ act,  // SMEM [k][4]
                                          int n, int g, float* accf) {
    unsigned long long acc01 = 0ull, acc23 = 0ull;
    uint32_t abase = (uint32_t)__cvta_generic_to_shared(act) + (uint32_t)(g * 128 * 16);
    const float* cwp = cw + (g * KC2) * HH + n;
    const float* wgp = wg + (g * 128 + KC2) * HH + n;
    #pragma unroll 8
    for (int kk = 0; kk < KC2; ++kk) {
        unsigned long long a01, a23;
        lds_v2u64(abase + (uint32_t)(kk * 16), a01, a23);
        unsigned long long ww = bcast2(cwp[kk * HH]);
        fma2(acc01, a01, ww);
        fma2(acc23, a23, ww);
    }
    #pragma unroll 8
    for (int kk = 0; kk < 128 - KC2; ++kk) {
        unsigned long long a01, a23;
        lds_v2u64(abase + (uint32_t)((KC2 + kk) * 16), a01, a23);
        unsigned long long ww = bcast2(__ldg(wgp + kk * HH));
        fma2(acc01, a01, ww);
        fma2(acc23, a23, ww);
    }
    unpack2(acc01, accf[0], accf[1]);
    unpack2(acc23, accf[2], accf[3]);
}

__global__ void __launch_bounds__(STH) k_scan(const float* __restrict__ h0,
                                              const float* __restrict__ bhid,
                                              const float* __restrict__ b2v,
                                              const float* __restrict__ b3v,
                                              const float* __restrict__ bout,
                                              float* __restrict__ out,
                                              int t0, int t1) {
    extern __shared__ float sm[];
    float* cwh  = sm;                        // [2*KC2][HH]
    float* cw2  = cwh + 2 * KC2 * HH;
    float* cw3  = cw2 + 2 * KC2 * HH;
    float* hs   = cw3 + 2 * KC2 * HH;        // [HH][4]
    float* actA = hs + HH * 4;               // [HH][4]
    float* actB = actA + HH * 4;             // [HH][4]
    float* wxs  = actB + HH * 4;             // [2][4*HH]
    float* pbuf = wxs + 2 * 4 * HH;          // [HH][4] partial sums

    int tid = threadIdx.x;
    int n = tid & 255;                       // output column
    int g = tid >> 8;                        // k-half
    int c = blockIdx.x;                      // row block

    // Fill weight cache: row r<KC2 -> k=r (half 0); r>=KC2 -> k=r+96 (half 1)
    for (int e = tid; e < 2 * KC2 * HH; e += STH) {
        int r = e >> 8;
        int k = (r < KC2) ? r : (r + 128 - KC2);
        int src = k * HH + (e & 255);
        cwh[e] = g_whid_t[src];
        cw2[e] = g_w2_t[src];
        cw3[e] = g_w3_t[src];
    }
    // Stage wx for t0 into buffer (t0&1)==0
    {
        const float* wxg0 = g_wx + ((size_t)t0 * BB + (size_t)c * 4) * HH;
        wxs[tid] = wxg0[tid];
        wxs[tid + STH] = wxg0[tid + STH];
    }

    float h[4] = {0.f, 0.f, 0.f, 0.f};
    if (g == 0) {
        const float* hsrc = (t0 == 0) ? h0 : g_h;
        #pragma unroll
        for (int r = 0; r < 4; ++r) h[r] = hsrc[(size_t)(c * 4 + r) * HH + n];
        *(float4*)&hs[n * 4] = make_float4(h[0], h[1], h[2], h[3]);
    }

    float bh = 0.f, bv2 = 0.f, bv3 = 0.f;
    if (g == 0) { bh = bhid[n]; bv2 = b2v[n]; bv3 = b3v[n]; }
    __syncthreads();

    for (int t = t0; t < t1; ++t) {
        float* cur = wxs + (t & 1) * (4 * HH);
        // Prefetch next step's wx into registers
        float pre[2];
        bool hasnext = (t + 1) < t1;
        if (hasnext) {
            const float* gp = g_wx + ((size_t)(t + 1) * BB + (size_t)c * 4) * HH;
            pre[0] = __ldg(gp + tid);
            pre[1] = __ldg(gp + tid + STH);
        }

        float acc[4];
        // G1: f1 = relu(2h @ W_hid^T + b_hid + wx)
        gemm_half(cwh, g_whid_t, hs, n, g, acc);
        if (g == 1) *(float4*)&pbuf[n * 4] = make_float4(acc[0], acc[1], acc[2], acc[3]);
        __syncthreads();
        if (g == 0) {
            float4 p = *(const float4*)&pbuf[n * 4];
            float f0 = fmaxf(acc[0] + p.x + bh + cur[n],          0.0f);
            float f1 = fmaxf(acc[1] + p.y + bh + cur[HH + n],     0.0f);
            float f2 = fmaxf(acc[2] + p.z + bh + cur[2 * HH + n], 0.0f);
            float f3 = fmaxf(acc[3] + p.w + bh + cur[3 * HH + n], 0.0f);
            *(float4*)&actA[n * 4] = make_float4(f0, f1, f2, f3);
        }
        __syncthreads();

        // G2: g2 = relu(f1 @ W2^T + b2)
        gemm_half(cw2, g_w2_t, actA, n, g, acc);
        if (g == 1) *(float4*)&pbuf[n * 4] = make_float4(acc[0], acc[1], acc[2], acc[3]);
        __syncthreads();
        if (g == 0) {
            float4 p = *(const float4*)&pbuf[n * 4];
            *(float4*)&actB[n * 4] = make_float4(fmaxf(acc[0] + p.x + bv2, 0.0f),
                                                 fmaxf(acc[1] + p.y + bv2, 0.0f),
                                                 fmaxf(acc[2] + p.z + bv2, 0.0f),
                                                 fmaxf(acc[3] + p.w + bv2, 0.0f));
        }
        __syncthreads();

        // G3: fn = relu(g2 @ W3^T + b3);  h <- 0.98 h + 0.01 fn
        gemm_half(cw3, g_w3_t, actB, n, g, acc);
        if (g == 1) *(float4*)&pbuf[n * 4] = make_float4(acc[0], acc[1], acc[2], acc[3]);
        __syncthreads();
        if (g == 0) {
            float4 p = *(const float4*)&pbuf[n * 4];
            #pragma unroll
            for (int r = 0; r < 4; ++r) {
                float pr = (r == 0) ? p.x : (r == 1) ? p.y : (r == 2) ? p.z : p.w;
                float fn = fmaxf(acc[r] + pr + bv3, 0.0f);
                h[r] = 0.98f * h[r] + 0.01f * fn;
            }
            *(float4*)&hs[n * 4] = make_float4(h[0], h[1], h[2], h[3]);
        }
        // Commit prefetched wx into the alternate buffer
        if (hasnext) {
            float* nb = wxs + ((t + 1) & 1) * (4 * HH);
            nb[tid] = pre[0];
            nb[tid + STH] = pre[1];
        }
        __syncthreads();
    }

    if (t1 < TT) {
        // Hand h off to the next segment
        if (g == 0) {
            #pragma unroll
            for (int r = 0; r < 4; ++r)
                g_h[(size_t)(c * 4 + r) * HH + n] = h[r];
        }
        return;
    }

    // Final segment: write h1 and y1
    if (g == 0) {
        #pragma unroll
        for (int r = 0; r < 4; ++r)
            out[(size_t)OO * BB + (size_t)(c * 4 + r) * HH + n] = h[r];
    }
    if (g == 0 && n < OO) {
        float bo = bout[n];
        float acc[4] = {bo, bo, bo, bo};
        #pragma unroll 8
        for (int k = 0; k < HH; ++k) {
            float4 a = *(const float4*)&hs[k * 4];
            float w = __ldg(g_wot + k * OO + n);
            acc[0] += a.x * w; acc[1] += a.y * w; acc[2] += a.z * w; acc[3] += a.w * w;
        }
        #pragma unroll
        for (int r = 0; r < 4; ++r)
            out[(size_t)(c * 4 + r) * OO + n] = acc[r];
    }
}

// ---------------------------------------------------------------------
// Launch: transpose, wx, then 4 scan segments (graph-capturable).
// Inputs: x0,h0,W_in,b_in,W_hid,b_hid,W2,b2,W3,b3,W_out,b_out
// Output: y1 [512,128] then h1 [512,256].
// ---------------------------------------------------------------------
extern "C" void kernel_launch(void* const* d_in, const int* in_sizes, int n_in,
                              void* d_out, int out_size) {
    const float* x0   = (const float*)d_in[0];
    const float* h0   = (const float*)d_in[1];
    const float* Win  = (const float*)d_in[2];
    const float* bin  = (const float*)d_in[3];
    const float* Whid = (const float*)d_in[4];
    const float* bhid = (const float*)d_in[5];
    const float* W2   = (const float*)d_in[6];
    const float* b2   = (const float*)d_in[7];
    const float* W3   = (const float*)d_in[8];
    const float* b3   = (const float*)d_in[9];
    const float* Wout = (const float*)d_in[10];
    const float* bout = (const float*)d_in[11];
    float* out = (float*)d_out;

    cudaFuncSetAttribute(k_wx,   cudaFuncAttributeMaxDynamicSharedMemorySize, WX_SMEM);
    cudaFuncSetAttribute(k_scan, cudaFuncAttributeMaxDynamicSharedMemorySize, SCAN_SMEM);

    k_transpose<<<256, 256>>>(Whid, W2, W3, Wout);
    k_wx<<<dim3(TT / 64, BB), 256, WX_SMEM>>>(x0, Win, bin);
    for (int s = 0; s < NSEG; ++s)
        k_scan<<<NCTA, STH, SCAN_SMEM>>>(h0, bhid, b2, b3, bout, out,
                                         s * SEGT, (s + 1) * SEGT);

    (void)in_sizes; (void)n_in; (void)out_size;
}

// round 11
// speedup vs baseline: 1.6461x; 1.4627x over previous
#include <cuda_runtime.h>
#include <cstddef>
#include <cstdint>

// Problem dims
#define TT 512
#define BB 512
#define FF 128
#define HH 256
#define OO 128

// Scan config: 128 CTAs x 4 batch rows, 512 threads.
// Thread (q = tid>>7, j = tid&127): k-quarter q (64 k-rows), columns {2j, 2j+1}.
#define MR 4
#define NCTA (BB / MR)
#define STH 512
// cached k-rows per quarter per matrix
#define CQ 15
// scan time segments
#define NSEG 4
#define SEGT (TT / NSEG)

// -------- device scratch (allocation-free: __device__ globals) --------
__device__ float g_wx[(size_t)TT * BB * HH];   // [t][b][h] input projection incl. b_in
__device__ float g_whid_t[HH * HH];            // (2*W_hid)^T as [k][n]
__device__ float g_w2_t[HH * HH];              // W2^T as [k][n]
__device__ float g_w3_t[HH * HH];              // W3^T as [k][n]
__device__ float g_wot[HH * OO];               // W_out^T as [k][o]
__device__ float g_h[BB * HH];                 // h state between scan segments

// ---------- f32x2 helpers ----------
__device__ __forceinline__ void fma2(unsigned long long& acc,
                                     unsigned long long a,
                                     unsigned long long b) {
    asm("fma.rn.f32x2 %0, %1, %2, %0;" : "+l"(acc) : "l"(a), "l"(b));
}
__device__ __forceinline__ unsigned long long bcast2(float w) {
    unsigned long long r;
    asm("mov.b64 %0, {%1, %1};" : "=l"(r) : "f"(w));
    return r;
}
__device__ __forceinline__ void unpack2(unsigned long long v, float& lo, float& hi) {
    asm("mov.b64 {%0, %1}, %2;" : "=f"(lo), "=f"(hi) : "l"(v));
}
__device__ __forceinline__ void lds_v2u64(uint32_t saddr,
                                          unsigned long long& a,
                                          unsigned long long& b) {
    asm("ld.shared.v2.u64 {%0, %1}, [%2];" : "=l"(a), "=l"(b) : "r"(saddr));
}

// ---------------------------------------------------------------------
// Kernel 0: transpose weights into [k][n] layout; fold (h+h) as x2.
// ---------------------------------------------------------------------
__global__ void k_transpose(const float* __restrict__ Whid,
                            const float* __restrict__ W2,
                            const float* __restrict__ W3,
                            const float* __restrict__ Wout) {
    int idx = blockIdx.x * 256 + threadIdx.x;
    if (idx < HH * HH) {
        int k = idx >> 8;
        int n = idx & 255;
        g_whid_t[idx] = 2.0f * Whid[n * HH + k];
        g_w2_t[idx]   = W2[n * HH + k];
        g_w3_t[idx]   = W3[n * HH + k];
    }
    if (idx < HH * OO) {
        int k = idx >> 7;
        int o = idx & 127;
        g_wot[idx] = Wout[o * HH + k];
    }
}

// ---------------------------------------------------------------------
// Kernel 1: WX[t][b][:] = x0[b,:,t] @ W_in.T + b_in  (unchanged; ~0.3ms)
// ---------------------------------------------------------------------
#define WINT_STRIDE 260
#define WX_SMEM ((FF * WINT_STRIDE + FF * 64) * 4)

__global__ void __launch_bounds__(256) k_wx(const float* __restrict__ x0,
                                            const float* __restrict__ Win,
                                            const float* __restrict__ bin) {
    extern __shared__ float sm[];
    float* wint = sm;
    float* xs   = sm + FF * WINT_STRIDE;

    int tb = blockIdx.x;
    int b  = blockIdx.y;
    int tid = threadIdx.x;

    for (int e = tid; e < HH * FF; e += 256) {
        int h = e >> 7, k = e & 127;
        wint[k * WINT_STRIDE + h] = Win[e];
    }
    const float* xb = x0 + (size_t)b * FF * TT + (size_t)tb * 64;
    for (int e = tid; e < FF * 64; e += 256) {
        int f = e >> 6, t = e & 63;
        xs[f * 64 + t] = xb[(size_t)f * TT + t];
    }
    __syncthreads();

    int ttg = tid & 3;
    int htg = tid >> 2;
    int h0 = htg * 4;
    int t0 = ttg * 16;

    uint32_t xs_base = (uint32_t)__cvta_generic_to_shared(xs) + (uint32_t)(t0 * 4);

    unsigned long long acc2[4][8];
    #pragma unroll
    for (int j = 0; j < 4; ++j)
        #pragma unroll
        for (int i = 0; i < 8; ++i) acc2[j][i] = 0ull;

    #pragma unroll 2
    for (int k = 0; k < FF; ++k) {
        float4 w4 = *(const float4*)&wint[k * WINT_STRIDE + h0];
        unsigned long long ww[4] = {bcast2(w4.x), bcast2(w4.y), bcast2(w4.z), bcast2(w4.w)};
        unsigned long long xp[8];
        uint32_t row = xs_base + (uint32_t)(k * 64 * 4);
        lds_v2u64(row,      xp[0], xp[1]);
        lds_v2u64(row + 16, xp[2], xp[3]);
        lds_v2u64(row + 32, xp[4], xp[5]);
        lds_v2u64(row + 48, xp[6], xp[7]);
        #pragma unroll
        for (int j = 0; j < 4; ++j)
            #pragma unroll
            for (int i = 0; i < 8; ++i)
                fma2(acc2[j][i], xp[i], ww[j]);
    }

    float bias[4];
    #pragma unroll
    for (int j = 0; j < 4; ++j) bias[j] = bin[h0 + j];

    #pragma unroll
    for (int i = 0; i < 8; ++i) {
        float lo[4], hi[4];
        #pragma unroll
        for (int j = 0; j < 4; ++j) unpack2(acc2[j][i], lo[j], hi[j]);
        int tg0 = tb * 64 + t0 + 2 * i;
        float4 v0 = make_float4(lo[0] + bias[0], lo[1] + bias[1], lo[2] + bias[2], lo[3] + bias[3]);
        float4 v1 = make_float4(hi[0] + bias[0], hi[1] + bias[1], hi[2] + bias[2], hi[3] + bias[3]);
        *(float4*)&g_wx[((size_t)tg0 * BB + b) * HH + h0]       = v0;
        *(float4*)&g_wx[((size_t)(tg0 + 1) * BB + b) * HH + h0] = v1;
    }
}

// ---------------------------------------------------------------------
// Kernel 2: scan segment over t in [t0,t1). 128 CTAs x 512 threads.
// Thread (q, j): partial dot over k in [64q, 64q+64) for cols {2j,2j+1},
// 4 rows. float2 weight loads (both cols, 1 LSU op). Quarters q=1..3
// write partials to pbuf; q=0 combines + epilogue. CQ rows/quarter of
// each weight cached in SMEM, rest streamed from L2.
// SMEM: 3*4*CQ*256 + 3*1024 + 2*1024 + 4096 floats = 221184 B
// ---------------------------------------------------------------------
#define SCAN_SMEM ((3 * 4 * CQ * HH + 3 * HH * 4 + 2 * 4 * HH + 4 * 128 * 8) * 4)

// Accumulate 4 rows x 2 cols over this thread's k-quarter.
__device__ __forceinline__ void gemm_q(const float* __restrict__ cwm,   // SMEM [4][CQ][HH]
                                       const float* __restrict__ wgm,   // gmem [HH][HH]
                                       const float* __restrict__ act,   // SMEM [k][4]
                                       int q, int j,
                                       float* a0, float* a1) {          // a0: rows, col0; a1: col1
    unsigned long long c010 = 0ull, c230 = 0ull, c011 = 0ull, c231 = 0ull;
    uint32_t abase = (uint32_t)__cvta_generic_to_shared(act) + (uint32_t)(q * 64 * 16);
    const float* cp = cwm + (q * CQ) * HH + 2 * j;
    const float* gp = wgm + (q * 64 + CQ) * HH + 2 * j;
    #pragma unroll 5
    for (int kk = 0; kk < CQ; ++kk) {
        unsigned long long x01, x23;
        lds_v2u64(abase + (uint32_t)(kk * 16), x01, x23);
        float2 w = *(const float2*)(cp + kk * HH);
        unsigned long long w0 = bcast2(w.x), w1 = bcast2(w.y);
        fma2(c010, x01, w0); fma2(c230, x23, w0);
        fma2(c011, x01, w1); fma2(c231, x23, w1);
    }
    #pragma unroll 7
    for (int kk = 0; kk < 64 - CQ; ++kk) {
        unsigned long long x01, x23;
        lds_v2u64(abase + (uint32_t)((CQ + kk) * 16), x01, x23);
        float2 w = __ldg((const float2*)(gp + kk * HH));
        unsigned long long w0 = bcast2(w.x), w1 = bcast2(w.y);
        fma2(c010, x01, w0); fma2(c230, x23, w0);
        fma2(c011, x01, w1); fma2(c231, x23, w1);
    }
    unpack2(c010, a0[0], a0[1]);
    unpack2(c230, a0[2], a0[3]);
    unpack2(c011, a1[0], a1[1]);
    unpack2(c231, a1[2], a1[3]);
}

__global__ void __launch_bounds__(STH) k_scan(const float* __restrict__ h0,
                                              const float* __restrict__ bhid,
                                              const float* __restrict__ b2v,
                                              const float* __restrict__ b3v,
                                              const float* __restrict__ bout,
                                              float* __restrict__ out,
                                              int t0, int t1) {
    extern __shared__ float sm[];
    float* cwh  = sm;                        // [4][CQ][HH]
    float* cw2  = cwh + 4 * CQ * HH;
    float* cw3  = cw2 + 4 * CQ * HH;
    float* hs   = cw3 + 4 * CQ * HH;         // [HH][4]
    float* actA = hs + HH * 4;               // [HH][4]
    float* actB = actA + HH * 4;             // [HH][4]
    float* wxs  = actB + HH * 4;             // [2][4*HH]
    float* pbuf = wxs + 2 * 4 * HH;          // [4][128][8]

    int tid = threadIdx.x;
    int q = tid >> 7;                        // k-quarter
    int j = tid & 127;                       // column pair (2j, 2j+1)
    int c = blockIdx.x;                      // row block

    // Fill weight cache: entry e -> quarter qq, local row kk, col n; k = qq*64+kk
    for (int e = tid; e < 4 * CQ * HH; e += STH) {
        int qq = e / (CQ * HH);
        int r  = e - qq * (CQ * HH);
        int kk = r >> 8;
        int n  = r & 255;
        int src = (qq * 64 + kk) * HH + n;
        cwh[e] = g_whid_t[src];
        cw2[e] = g_w2_t[src];
        cw3[e] = g_w3_t[src];
    }
    // Stage wx for t0 into buffer (t0 & 1)
    {
        const float* wxg0 = g_wx + ((size_t)t0 * BB + (size_t)c * 4) * HH;
        float* b0 = wxs + (t0 & 1) * (4 * HH);
        b0[tid] = wxg0[tid];
        b0[tid + STH] = wxg0[tid + STH];
    }

    // h state: held by q==0 threads, [row][col0/1]
    float h0r[4], h1r[4];
    if (q == 0) {
        const float* hsrc = (t0 == 0) ? h0 : g_h;
        #pragma unroll
        for (int r = 0; r < 4; ++r) {
            float2 hv = *(const float2*)&hsrc[(size_t)(c * 4 + r) * HH + 2 * j];
            h0r[r] = hv.x; h1r[r] = hv.y;
        }
        *(float4*)&hs[(2 * j) * 4]     = make_float4(h0r[0], h0r[1], h0r[2], h0r[3]);
        *(float4*)&hs[(2 * j + 1) * 4] = make_float4(h1r[0], h1r[1], h1r[2], h1r[3]);
    }

    float bh0 = 0.f, bh1 = 0.f, b20 = 0.f, b21 = 0.f, b30 = 0.f, b31 = 0.f;
    if (q == 0) {
        float2 v;
        v = *(const float2*)&bhid[2 * j]; bh0 = v.x; bh1 = v.y;
        v = *(const float2*)&b2v[2 * j];  b20 = v.x; b21 = v.y;
        v = *(const float2*)&b3v[2 * j];  b30 = v.x; b31 = v.y;
    }
    __syncthreads();

    float* myp = pbuf + (q * 128 + j) * 8;

    for (int t = t0; t < t1; ++t) {
        float* cur = wxs + (t & 1) * (4 * HH);
        // Prefetch next step's wx
        float pre0 = 0.f, pre1 = 0.f;
        bool hasnext = (t + 1) < t1;
        if (hasnext) {
            const float* gp = g_wx + ((size_t)(t + 1) * BB + (size_t)c * 4) * HH;
            pre0 = __ldg(gp + tid);
            pre1 = __ldg(gp + tid + STH);
        }

        float a0[4], a1[4];

        // ---- G1: f1 = relu(2h @ W_hid^T + b_hid + wx) ----
        gemm_q(cwh, g_whid_t, hs, q, j, a0, a1);
        if (q != 0) {
            *(float4*)&myp[0] = make_float4(a0[0], a0[1], a0[2], a0[3]);
            *(float4*)&myp[4] = make_float4(a1[0], a1[1], a1[2], a1[3]);
        }
        __syncthreads();
        if (q == 0) {
            #pragma unroll
            for (int p = 1; p < 4; ++p) {
                const float* pp = pbuf + (p * 128 + j) * 8;
                float4 s0 = *(const float4*)&pp[0];
                float4 s1 = *(const float4*)&pp[4];
                a0[0] += s0.x; a0[1] += s0.y; a0[2] += s0.z; a0[3] += s0.w;
                a1[0] += s1.x; a1[1] += s1.y; a1[2] += s1.z; a1[3] += s1.w;
            }
            float f00[4], f11[4];
            #pragma unroll
            for (int r = 0; r < 4; ++r) {
                float2 wxv = *(const float2*)&cur[r * HH + 2 * j];
                f00[r] = fmaxf(a0[r] + bh0 + wxv.x, 0.0f);
                f11[r] = fmaxf(a1[r] + bh1 + wxv.y, 0.0f);
            }
            *(float4*)&actA[(2 * j) * 4]     = make_float4(f00[0], f00[1], f00[2], f00[3]);
            *(float4*)&actA[(2 * j + 1) * 4] = make_float4(f11[0], f11[1], f11[2], f11[3]);
        }
        __syncthreads();

        // ---- G2: g2 = relu(f1 @ W2^T + b2) ----
        gemm_q(cw2, g_w2_t, actA, q, j, a0, a1);
        if (q != 0) {
            *(float4*)&myp[0] = make_float4(a0[0], a0[1], a0[2], a0[3]);
            *(float4*)&myp[4] = make_float4(a1[0], a1[1], a1[2], a1[3]);
        }
        __syncthreads();
        if (q == 0) {
            #pragma unroll
            for (int p = 1; p < 4; ++p) {
                const float* pp = pbuf + (p * 128 + j) * 8;
                float4 s0 = *(const float4*)&pp[0];
                float4 s1 = *(const float4*)&pp[4];
                a0[0] += s0.x; a0[1] += s0.y; a0[2] += s0.z; a0[3] += s0.w;
                a1[0] += s1.x; a1[1] += s1.y; a1[2] += s1.z; a1[3] += s1.w;
            }
            *(float4*)&actB[(2 * j) * 4] = make_float4(fmaxf(a0[0] + b20, 0.f),
                                                       fmaxf(a0[1] + b20, 0.f),
                                                       fmaxf(a0[2] + b20, 0.f),
                                                       fmaxf(a0[3] + b20, 0.f));
            *(float4*)&actB[(2 * j + 1) * 4] = make_float4(fmaxf(a1[0] + b21, 0.f),
                                                           fmaxf(a1[1] + b21, 0.f),
                                                           fmaxf(a1[2] + b21, 0.f),
                                                           fmaxf(a1[3] + b21, 0.f));
        }
        __syncthreads();

        // ---- G3: fn = relu(g2 @ W3^T + b3);  h <- 0.98 h + 0.01 fn ----
        gemm_q(cw3, g_w3_t, actB, q, j, a0, a1);
        if (q != 0) {
            *(float4*)&myp[0] = make_float4(a0[0], a0[1], a0[2], a0[3]);
            *(float4*)&myp[4] = make_float4(a1[0], a1[1], a1[2], a1[3]);
        }
        // Commit prefetched wx (other buffer; its last read was step t-1's G1)
        if (hasnext) {
            float* nb = wxs + ((t + 1) & 1) * (4 * HH);
            nb[tid] = pre0;
            nb[tid + STH] = pre1;
        }
        __syncthreads();
        if (q == 0) {
            #pragma unroll
            for (int p = 1; p < 4; ++p) {
                const float* pp = pbuf + (p * 128 + j) * 8;
                float4 s0 = *(const float4*)&pp[0];
                float4 s1 = *(const float4*)&pp[4];
                a0[0] += s0.x; a0[1] += s0.y; a0[2] += s0.z; a0[3] += s0.w;
                a1[0] += s1.x; a1[1] += s1.y; a1[2] += s1.z; a1[3] += s1.w;
            }
            #pragma unroll
            for (int r = 0; r < 4; ++r) {
                float fn0 = fmaxf(a0[r] + b30, 0.0f);
                float fn1 = fmaxf(a1[r] + b31, 0.0f);
                h0r[r] = 0.98f * h0r[r] + 0.01f * fn0;
                h1r[r] = 0.98f * h1r[r] + 0.01f * fn1;
            }
            *(float4*)&hs[(2 * j) * 4]     = make_float4(h0r[0], h0r[1], h0r[2], h0r[3]);
            *(float4*)&hs[(2 * j + 1) * 4] = make_float4(h1r[0], h1r[1], h1r[2], h1r[3]);
        }
        __syncthreads();
    }

    if (t1 < TT) {
        // Hand h off to the next segment
        if (q == 0) {
            #pragma unroll
            for (int r = 0; r < 4; ++r) {
                float2 hv = make_float2(h0r[r], h1r[r]);
                *(float2*)&g_h[(size_t)(c * 4 + r) * HH + 2 * j] = hv;
            }
        }
        return;
    }

    // Final segment: write h1 and y1
    if (q == 0) {
        #pragma unroll
        for (int r = 0; r < 4; ++r) {
            float2 hv = make_float2(h0r[r], h1r[r]);
            *(float2*)&out[(size_t)OO * BB + (size_t)(c * 4 + r) * HH + 2 * j] = hv;
        }
    }
    if (tid < OO) {
        int n = tid;
        float bo = bout[n];
        float acc[4] = {bo, bo, bo, bo};
        #pragma unroll 8
        for (int k = 0; k < HH; ++k) {
            float4 a = *(const float4*)&hs[k * 4];
            float w = __ldg(g_wot + k * OO + n);
            acc[0] += a.x * w; acc[1] += a.y * w; acc[2] += a.z * w; acc[3] += a.w * w;
        }
        #pragma unroll
        for (int r = 0; r < 4; ++r)
            out[(size_t)(c * 4 + r) * OO + n] = acc[r];
    }
}

// ---------------------------------------------------------------------
// Launch: transpose, wx, then 4 scan segments (graph-capturable).
// Inputs: x0,h0,W_in,b_in,W_hid,b_hid,W2,b2,W3,b3,W_out,b_out
// Output: y1 [512,128] then h1 [512,256].
// ---------------------------------------------------------------------
extern "C" void kernel_launch(void* const* d_in, const int* in_sizes, int n_in,
                              void* d_out, int out_size) {
    const float* x0   = (const float*)d_in[0];
    const float* h0   = (const float*)d_in[1];
    const float* Win  = (const float*)d_in[2];
    const float* bin  = (const float*)d_in[3];
    const float* Whid = (const float*)d_in[4];
    const float* bhid = (const float*)d_in[5];
    const float* W2   = (const float*)d_in[6];
    const float* b2   = (const float*)d_in[7];
    const float* W3   = (const float*)d_in[8];
    const float* b3   = (const float*)d_in[9];
    const float* Wout = (const float*)d_in[10];
    const float* bout = (const float*)d_in[11];
    float* out = (float*)d_out;

    cudaFuncSetAttribute(k_wx,   cudaFuncAttributeMaxDynamicSharedMemorySize, WX_SMEM);
    cudaFuncSetAttribute(k_scan, cudaFuncAttributeMaxDynamicSharedMemorySize, SCAN_SMEM);

    k_transpose<<<256, 256>>>(Whid, W2, W3, Wout);
    k_wx<<<dim3(TT / 64, BB), 256, WX_SMEM>>>(x0, Win, bin);
    for (int s = 0; s < NSEG; ++s)
        k_scan<<<NCTA, STH, SCAN_SMEM>>>(h0, bhid, b2, b3, bout, out,
                                         s * SEGT, (s + 1) * SEGT);

    (void)in_sizes; (void)n_in; (void)out_size;
}